// round 12
// baseline (speedup 1.0000x reference)
#include <cuda_runtime.h>
#include <math.h>
#include <stdint.h>

// ----------------------------------------------------------------------------
// GaussianScene: key_kernel -> 3x9-bit onesweep sort (last pass emits INVERSE
// permutation rank[i]) -> finalize in INPUT order with scattered row writes.
// Key remap: in-view zview bit patterns lie in [0x3E4CCCCD, 0x41800000)
// (zview in [0.2,16)); key27 = bits - 0x3E000000 < 2^26. out-of-view -> max.
// ----------------------------------------------------------------------------

#define N_MAX   2100000
#define NCOLS   21
#define SORT_THREADS 512
#define WARPS   16
#define SORT_EPT     8
#define SORT_TILE    (SORT_THREADS * SORT_EPT)   // 4096
#define CHUNK   (SORT_TILE / WARPS)              // 256 per warp
#define MAX_NB  ((N_MAX + SORT_TILE - 1) / SORT_TILE + 1)
#define NBINS   512
#define NPASS   3

#define AGG_FLAG 0x40000000u
#define INC_FLAG 0x80000000u
#define VAL_MASK 0x3FFFFFFFu

__device__ uint2    g_kvA[N_MAX];
__device__ uint2    g_kvB[N_MAX];
__device__ unsigned g_rank[N_MAX];                  // rank[i] = sorted position of i
__device__ unsigned g_lb[NPASS * MAX_NB * NBINS];   // lookback status (memset 0)
__device__ unsigned g_gh[NPASS * NBINS];            // global digit hists (memset 0)
__device__ unsigned g_base[NPASS * NBINS];          // exclusive digit bases

__device__ __forceinline__ void wagg_add(unsigned* bin, unsigned d, unsigned am, int lane)
{
    unsigned peers = __match_any_sync(am, d);
    int leader = __ffs(peers) - 1;
    if (lane == leader) atomicAdd(&bin[d], (unsigned)__popc(peers));
}

// ----------------------------------------------------------------------------
// 1) key_kernel: depth key + (key,idx) + fused 3-pass histogram (pts only)
// ----------------------------------------------------------------------------
__global__ __launch_bounds__(256)
void key_kernel(const float* __restrict__ pts,
                const float* __restrict__ V,
                int n)
{
    __shared__ unsigned h[NPASS * NBINS];
    #pragma unroll
    for (int k = threadIdx.x; k < NPASS * NBINS; k += 256) h[k] = 0;
    __syncthreads();

    int i = blockIdx.x * blockDim.x + threadIdx.x;
    int lane = threadIdx.x & 31;

    if (i < n) {
        float px_ = pts[3*i+0], py_ = pts[3*i+1], pz_ = pts[3*i+2];
        float zview = px_*V[2] + py_*V[6] + pz_*V[10] + V[14];
        bool in_view = (zview >= 0.2f);
        unsigned k;
        if (in_view) {
            unsigned b = __float_as_uint(zview);
            k = (b >= 0x41800000u) ? 0x07FFFFFEu : (b - 0x3E000000u);
        } else {
            k = 0x07FFFFFFu;
        }
        g_kvA[i] = make_uint2(k, (unsigned)i);
        unsigned am = __activemask();
        wagg_add(&h[0*NBINS], k         & 511u, am, lane);
        wagg_add(&h[1*NBINS], (k >> 9)  & 511u, am, lane);
        wagg_add(&h[2*NBINS], (k >> 18) & 511u, am, lane);
    }
    __syncthreads();

    #pragma unroll
    for (int k = threadIdx.x; k < NPASS * NBINS; k += 256) {
        unsigned c = h[k];
        if (c) atomicAdd(&g_gh[k], c);
    }
}

// ----------------------------------------------------------------------------
// 2a) exclusive scan of each pass's 512-bin global histogram (512 threads)
// ----------------------------------------------------------------------------
__global__ __launch_bounds__(NBINS)
void scanP_kernel()
{
    __shared__ unsigned ws[WARPS];
    int lane = threadIdx.x & 31, warp = threadIdx.x >> 5;
    for (int p = 0; p < NPASS; p++) {
        unsigned v = g_gh[p * NBINS + threadIdx.x];
        unsigned x = v;
        #pragma unroll
        for (int o = 1; o < 32; o <<= 1) {
            unsigned t = __shfl_up_sync(0xffffffffu, x, o);
            if (lane >= o) x += t;
        }
        if (lane == 31) ws[warp] = x;
        __syncthreads();
        if (warp == 0 && lane < WARPS) {
            unsigned s = ws[lane];
            #pragma unroll
            for (int o = 1; o < WARPS; o <<= 1) {
                unsigned t = __shfl_up_sync(0xffffu, s, o);
                if (lane >= o) s += t;
            }
            ws[lane] = s;
        }
        __syncthreads();
        unsigned wbase = (warp == 0) ? 0u : ws[warp - 1];
        g_base[p * NBINS + threadIdx.x] = wbase + x - v;
        __syncthreads();
    }
}

// ----------------------------------------------------------------------------
// 2b) onesweep scatter: 512 threads, 16 warps x 256-elem chunks, EPT=8,
//     512 bins (tid == digit). Last pass emits INVERSE perm: rank[idx]=pos.
// ----------------------------------------------------------------------------
__global__ __launch_bounds__(SORT_THREADS)
void scatter_os_kernel(const uint2* __restrict__ kvin,
                       uint2* __restrict__ kvout,
                       unsigned* __restrict__ rankout,
                       int n, int shift, int pass, int last)
{
    __shared__ unsigned short warpCnt[WARPS][NBINS];
    __shared__ uint2          sKV[SORT_TILE];
    __shared__ unsigned       sGlob[NBINS];
    __shared__ unsigned       sLoc[NBINS];
    __shared__ unsigned       ws[WARPS];

    int tid = threadIdx.x, warp = tid >> 5, lane = tid & 31;
    int bid = blockIdx.x;
    int base = bid * SORT_TILE;
    int m = n - base; if (m > SORT_TILE) m = SORT_TILE;
    unsigned ltmask = (1u << lane) - 1u;

    unsigned* lb = g_lb + (size_t)pass * (MAX_NB * NBINS);

    #pragma unroll
    for (int k = tid; k < WARPS * NBINS; k += SORT_THREADS)
        ((unsigned short*)warpCnt)[k] = 0;
    __syncthreads();

    // --- warp-sequential ranking: warp w owns [base + w*256, +256) ---
    int wbase = base + warp * CHUNK;
    uint2          kv[SORT_EPT];
    unsigned short posw[SORT_EPT];

    #pragma unroll
    for (int r = 0; r < SORT_EPT; r++) {
        int idx = wbase + r * 32 + lane;
        bool valid = (idx < n);
        uint2 v = valid ? kvin[idx] : make_uint2(0u, 0u);
        kv[r] = v;
        unsigned d = (v.x >> shift) & 511u;
        unsigned vm    = __ballot_sync(0xffffffffu, valid);
        unsigned peers = __match_any_sync(0xffffffffu, d) & vm;
        unsigned rank  = __popc(peers & ltmask);
        int leader = __ffs(peers) - 1;
        unsigned cbase = 0;
        if (valid && lane == (unsigned)leader) {
            cbase = warpCnt[warp][d];
            warpCnt[warp][d] = (unsigned short)(cbase + __popc(peers));
        }
        cbase = __shfl_sync(0xffffffffu, cbase, leader & 31);
        posw[r] = (unsigned short)(cbase + rank);
        __syncwarp(0xffffffffu);
    }
    __syncthreads();

    // --- block digit totals + per-warp offsets (thread tid owns digit tid) ---
    unsigned c[WARPS];
    unsigned cnt = 0;
    #pragma unroll
    for (int w = 0; w < WARPS; w++) { c[w] = warpCnt[w][tid]; cnt += c[w]; }

    atomicExch(&lb[(size_t)bid * NBINS + tid],
               cnt | (bid == 0 ? INC_FLAG : AGG_FLAG));

    unsigned x = cnt;
    #pragma unroll
    for (int o = 1; o < 32; o <<= 1) {
        unsigned t = __shfl_up_sync(0xffffffffu, x, o);
        if (lane >= o) x += t;
    }
    if (lane == 31) ws[warp] = x;
    __syncthreads();
    if (warp == 0 && lane < WARPS) {
        unsigned s = ws[lane];
        #pragma unroll
        for (int o = 1; o < WARPS; o <<= 1) {
            unsigned t = __shfl_up_sync(0xffffu, s, o);
            if (lane >= o) s += t;
        }
        ws[lane] = s;
    }
    __syncthreads();
    {
        unsigned wb = (warp == 0) ? 0u : ws[warp - 1];
        unsigned loc = wb + x - cnt;
        sLoc[tid] = loc;
        unsigned acc = loc;
        #pragma unroll
        for (int w = 0; w < WARPS; w++) { warpCnt[w][tid] = (unsigned short)acc; acc += c[w]; }
    }
    __syncthreads();

    #pragma unroll
    for (int r = 0; r < SORT_EPT; r++) {
        int idx = wbase + r * 32 + lane;
        if (idx < n) {
            unsigned d = (kv[r].x >> shift) & 511u;
            unsigned p = (unsigned)warpCnt[warp][d] + (unsigned)posw[r];
            sKV[p] = kv[r];
        }
    }

    // --- decoupled lookback (thread tid owns digit tid) ---
    {
        unsigned excl = 0;
        if (bid > 0) {
            volatile unsigned* vlb = (volatile unsigned*)lb;
            int j = bid - 1;
            bool done = false;
            while (!done) {
                unsigned sv[8];
                int take = (j + 1 < 8) ? (j + 1) : 8;
                #pragma unroll
                for (int t = 0; t < 8; t++)
                    if (t < take) sv[t] = vlb[(size_t)(j - t) * NBINS + tid];
                for (int t = 0; t < take; t++) {
                    unsigned v = sv[t];
                    while (v < AGG_FLAG) v = vlb[(size_t)(j - t) * NBINS + tid];
                    excl += v & VAL_MASK;
                    if (v >= INC_FLAG) { done = true; break; }
                }
                j -= take;
                if (j < 0) done = true;
            }
            atomicExch(&lb[(size_t)bid * NBINS + tid], (excl + cnt) | INC_FLAG);
        }
        sGlob[tid] = g_base[pass * NBINS + tid] + excl;
    }
    __syncthreads();

    // --- emit ---
    if (last) {
        // inverse permutation: rank[original_index] = sorted position
        for (int j = tid; j < m; j += SORT_THREADS) {
            uint2 v = sKV[j];
            unsigned d = (v.x >> shift) & 511u;
            rankout[v.y] = sGlob[d] + ((unsigned)j - sLoc[d]);
        }
    } else {
        for (int j = tid; j < m; j += SORT_THREADS) {
            uint2 v = sKV[j];
            unsigned d = (v.x >> shift) & 511u;
            kvout[sGlob[d] + ((unsigned)j - sLoc[d])] = v;
        }
    }
}

// ----------------------------------------------------------------------------
// 3) finalize: INPUT order — coalesced reads of the raw inputs, full
//    recompute, scattered 84B row write to out[rank[i]]
// ----------------------------------------------------------------------------
__global__ __launch_bounds__(256)
void finalize_kernel(const unsigned* __restrict__ rank,
                     const float* __restrict__ pts,
                     const float* __restrict__ cols,
                     const float* __restrict__ opa,
                     const float* __restrict__ scl,
                     const float* __restrict__ quat,
                     const float* __restrict__ V,
                     const float* __restrict__ F,
                     const float* __restrict__ tanxp,
                     const float* __restrict__ tanyp,
                     const float* __restrict__ fxp,
                     const float* __restrict__ fyp,
                     const int*   __restrict__ wptr,
                     const int*   __restrict__ hptr,
                     float* __restrict__ out,
                     int n)
{
    int i = blockIdx.x * blockDim.x + threadIdx.x;
    if (i >= n) return;

    float tanX = tanxp[0], tanY = tanyp[0];
    float fx = fxp[0], fy = fyp[0];
    float Wd = (float)wptr[0];
    float Hd = (float)hptr[0];

    float px_ = pts[3*i+0], py_ = pts[3*i+1], pz_ = pts[3*i+2];

    float4 q = ((const float4*)quat)[i];
    float qw = q.x, qx = q.y, qy = q.z, qz = q.w;
    float qn = rsqrtf(qw*qw + qx*qx + qy*qy + qz*qz);
    qw *= qn; qx *= qn; qy *= qn; qz *= qn;
    float R00 = 1.f - 2.f*(qy*qy + qz*qz);
    float R01 = 2.f*(qx*qy - qw*qz);
    float R02 = 2.f*(qx*qz + qw*qy);
    float R10 = 2.f*(qx*qy + qw*qz);
    float R11 = 1.f - 2.f*(qx*qx + qz*qz);
    float R12 = 2.f*(qy*qz - qw*qx);
    float R20 = 2.f*(qx*qz - qw*qy);
    float R21 = 2.f*(qy*qz + qw*qx);
    float R22 = 1.f - 2.f*(qx*qx + qy*qy);

    float s0 = scl[3*i+0], s1 = scl[3*i+1], s2 = scl[3*i+2];
    float M00 = R00*s0, M01 = R01*s1, M02 = R02*s2;
    float M10 = R10*s0, M11 = R11*s1, M12 = R12*s2;
    float M20 = R20*s0, M21 = R21*s1, M22 = R22*s2;
    float C00 = M00*M00 + M01*M01 + M02*M02;
    float C01 = M00*M10 + M01*M11 + M02*M12;
    float C02 = M00*M20 + M01*M21 + M02*M22;
    float C11 = M10*M10 + M11*M11 + M12*M12;
    float C12 = M10*M20 + M11*M21 + M12*M22;
    float C22 = M20*M20 + M21*M21 + M22*M22;

    float pvx = px_*V[0] + py_*V[4] + pz_*V[8]  + V[12];
    float pvy = px_*V[1] + py_*V[5] + pz_*V[9]  + V[13];
    float pvz = px_*V[2] + py_*V[6] + pz_*V[10] + V[14];
    float zview = pvz;
    bool in_view = (zview >= 0.2f);

    float cx = px_*F[0] + py_*F[4] + pz_*F[8]  + F[12];
    float cy = px_*F[1] + py_*F[5] + pz_*F[9]  + F[13];
    float cw = px_*F[3] + py_*F[7] + pz_*F[11] + F[15];
    float ndx = cx / cw;
    float ndy = cy / cw;
    float px = ((ndx + 1.f) * Wd - 1.f) * 0.5f;
    float py = ((ndy + 1.f) * Hd - 1.f) * 0.5f;

    float limx = 1.3f * tanX, limy = 1.3f * tanY;
    float xc = fminf(fmaxf(pvx / zview, -limx), limx) * zview;
    float yc = fminf(fmaxf(pvy / zview, -limy), limy) * zview;
    float z2 = zview * zview;

    float J00 = fx / zview;
    float J02 = -(fx * xc) / z2;
    float J11 = fy / zview;
    float J12 = -(fy * yc) / z2;

    float T00 = J00*V[0] + J02*V[2];
    float T01 = J00*V[4] + J02*V[6];
    float T02 = J00*V[8] + J02*V[10];
    float T10 = J11*V[1] + J12*V[2];
    float T11 = J11*V[5] + J12*V[6];
    float T12 = J11*V[9] + J12*V[10];

    float a00 = T00*C00 + T01*C01 + T02*C02;
    float a01 = T00*C01 + T01*C11 + T02*C12;
    float a02 = T00*C02 + T01*C12 + T02*C22;
    float a10 = T10*C00 + T11*C01 + T12*C02;
    float a11 = T10*C01 + T11*C11 + T12*C12;
    float a12 = T10*C02 + T11*C12 + T12*C22;

    float c00 = a00*T00 + a01*T01 + a02*T02;
    float c01 = a00*T10 + a01*T11 + a02*T12;
    float c10 = a10*T00 + a11*T01 + a12*T02;
    float c11 = a10*T10 + a11*T11 + a12*T12;

    float det = c00*c11 - c01*c10;
    float det_safe = (fabsf(det) < 1e-6f) ? 1e-6f : det;
    float ic0 =  c11 / det_safe;
    float ic1 = -c01 / det_safe;
    float ic2 = -c10 / det_safe;
    float ic3 =  c00 / det_safe;

    float mid = 0.5f * (c00 + c11);
    float inter = fmaxf(mid*mid - det, 0.1f);
    float lam = mid + sqrtf(inter);
    float radius = ceilf(3.0f * sqrtf(fmaxf(lam, 0.f)));
    float min_x = floorf(px - radius);
    float min_y = floorf(py - radius);
    float max_x = ceilf(px + radius);
    float max_y = ceilf(py + radius);

    float o = opa[i];
    float sig;
    if (o >= 0.f) { sig = 1.f / (1.f + expf(-o)); }
    else          { float e = expf(o); sig = e / (1.f + e); }

    float* dst = out + (size_t)rank[i] * NCOLS;
    dst[0]  = px;     dst[1]  = py;     dst[2]  = zview;
    dst[3]  = c00;    dst[4]  = c01;    dst[5]  = c10;    dst[6] = c11;
    dst[7]  = ic0;    dst[8]  = ic1;    dst[9]  = ic2;    dst[10] = ic3;
    dst[11] = radius;
    dst[12] = min_x;  dst[13] = min_y;  dst[14] = max_x;  dst[15] = max_y;
    dst[16] = cols[3*i+0]; dst[17] = cols[3*i+1]; dst[18] = cols[3*i+2];
    dst[19] = sig;
    dst[20] = in_view ? 1.f : 0.f;
}

// ----------------------------------------------------------------------------
extern "C" void kernel_launch(void* const* d_in, const int* in_sizes, int n_in,
                              void* d_out, int out_size)
{
    const float* pts  = (const float*)d_in[0];
    const float* cols = (const float*)d_in[1];
    const float* opa  = (const float*)d_in[2];
    const float* scl  = (const float*)d_in[3];
    const float* quat = (const float*)d_in[4];
    const float* V    = (const float*)d_in[5];
    const float* F    = (const float*)d_in[6];
    const float* tanx = (const float*)d_in[7];
    const float* tany = (const float*)d_in[8];
    const float* fx   = (const float*)d_in[9];
    const float* fy   = (const float*)d_in[10];
    const int*   wp   = (const int*)d_in[11];
    const int*   hp   = (const int*)d_in[12];
    float* out = (float*)d_out;

    int n = in_sizes[2];
    if (n <= 0 || n > N_MAX) return;
    (void)n_in; (void)out_size;

    static uint2 *kvA = nullptr, *kvB = nullptr;
    static unsigned *rankp = nullptr;
    static void *lbp = nullptr, *ghp = nullptr;
    if (!kvA) {
        cudaGetSymbolAddress((void**)&kvA, g_kvA);
        cudaGetSymbolAddress((void**)&kvB, g_kvB);
        cudaGetSymbolAddress((void**)&rankp, g_rank);
        cudaGetSymbolAddress(&lbp, g_lb);
        cudaGetSymbolAddress(&ghp, g_gh);
    }

    int nb = (n + SORT_TILE - 1) / SORT_TILE;
    int blocks = (n + 255) / 256;

    cudaMemsetAsync(lbp, 0, sizeof(unsigned) * NPASS * MAX_NB * NBINS);
    cudaMemsetAsync(ghp, 0, sizeof(unsigned) * NPASS * NBINS);

    key_kernel<<<blocks, 256>>>(pts, V, n);
    scanP_kernel<<<1, NBINS>>>();

    uint2* kin = kvA;  uint2* kout = kvB;
    for (int p = 0; p < NPASS; p++) {
        int last = (p == NPASS - 1);
        scatter_os_kernel<<<nb, SORT_THREADS>>>(kin, kout, rankp,
                                                n, p * 9, p, last);
        uint2* t = kin; kin = kout; kout = t;
    }

    finalize_kernel<<<blocks, 256>>>(rankp, pts, cols, opa, scl, quat, V, F,
                                     tanx, tany, fx, fy, wp, hp, out, n);
}

// round 13
// speedup vs baseline: 2.1117x; 2.1117x over previous
#include <cuda_runtime.h>
#include <math.h>
#include <stdint.h>

// ----------------------------------------------------------------------------
// GaussianScene: prep(pack 64B rows + key + hist) -> 3x9-bit onesweep sort
// (last pass emits index-only) -> finalize (gather 64B row, recompute,
// coalesced store).
// Key remap: in-view zview bit patterns lie in [0x3E4CCCCD, 0x41800000)
// (zview in [0.2,16)); key27 = bits - 0x3E000000 < 2^26. out-of-view -> max.
// ----------------------------------------------------------------------------

#define N_MAX   2100000
#define NCOLS   21
#define SORT_THREADS 512
#define WARPS   16
#define SORT_EPT     8
#define SORT_TILE    (SORT_THREADS * SORT_EPT)   // 4096
#define CHUNK   (SORT_TILE / WARPS)              // 256 per warp
#define MAX_NB  ((N_MAX + SORT_TILE - 1) / SORT_TILE + 1)
#define NBINS   512
#define NPASS   3

#define AGG_FLAG 0x40000000u
#define INC_FLAG 0x80000000u
#define VAL_MASK 0x3FFFFFFFu

__device__ float4   g_pk[(size_t)N_MAX * 4];        // 64B packed input rows
__device__ uint2    g_kvA[N_MAX];
__device__ uint2    g_kvB[N_MAX];
__device__ unsigned g_idx[N_MAX];                   // final sorted indices
__device__ unsigned g_lb[NPASS * MAX_NB * NBINS];   // lookback status (memset 0)
__device__ unsigned g_gh[NPASS * NBINS];            // global digit hists (memset 0)
__device__ unsigned g_base[NPASS * NBINS];          // exclusive digit bases

__device__ __forceinline__ void wagg_add(unsigned* bin, unsigned d, unsigned am, int lane)
{
    unsigned peers = __match_any_sync(am, d);
    int leader = __ffs(peers) - 1;
    if (lane == leader) atomicAdd(&bin[d], (unsigned)__popc(peers));
}

// ----------------------------------------------------------------------------
// 1) prep: pack 16-float input row + depth key + fused 3-pass histogram
// ----------------------------------------------------------------------------
__global__ __launch_bounds__(256)
void prep_kernel(const float* __restrict__ pts,
                 const float* __restrict__ cols,
                 const float* __restrict__ opa,
                 const float* __restrict__ scl,
                 const float* __restrict__ quat,
                 const float* __restrict__ V,
                 int n)
{
    __shared__ unsigned h[NPASS * NBINS];
    #pragma unroll
    for (int k = threadIdx.x; k < NPASS * NBINS; k += 256) h[k] = 0;
    __syncthreads();

    int i = blockIdx.x * blockDim.x + threadIdx.x;
    int lane = threadIdx.x & 31;

    if (i < n) {
        float px_ = pts[3*i+0], py_ = pts[3*i+1], pz_ = pts[3*i+2];
        float4 q  = ((const float4*)quat)[i];
        float s0 = scl[3*i+0], s1 = scl[3*i+1], s2 = scl[3*i+2];
        float c0 = cols[3*i+0], c1 = cols[3*i+1], c2 = cols[3*i+2];
        float o  = opa[i];

        float zview = px_*V[2] + py_*V[6] + pz_*V[10] + V[14];
        bool in_view = (zview >= 0.2f);
        unsigned k;
        if (in_view) {
            unsigned b = __float_as_uint(zview);
            k = (b >= 0x41800000u) ? 0x07FFFFFEu : (b - 0x3E000000u);
        } else {
            k = 0x07FFFFFFu;
        }
        g_kvA[i] = make_uint2(k, (unsigned)i);

        float4* dst = g_pk + (size_t)i * 4;
        dst[0] = make_float4(px_, py_, pz_, q.x);
        dst[1] = make_float4(q.y, q.z, q.w, s0);
        dst[2] = make_float4(s1, s2, c0, c1);
        dst[3] = make_float4(c2, o, 0.f, 0.f);

        unsigned am = __activemask();
        wagg_add(&h[0*NBINS], k         & 511u, am, lane);
        wagg_add(&h[1*NBINS], (k >> 9)  & 511u, am, lane);
        wagg_add(&h[2*NBINS], (k >> 18) & 511u, am, lane);
    }
    __syncthreads();

    #pragma unroll
    for (int k = threadIdx.x; k < NPASS * NBINS; k += 256) {
        unsigned c = h[k];
        if (c) atomicAdd(&g_gh[k], c);
    }
}

// ----------------------------------------------------------------------------
// 2a) exclusive scan of each pass's 512-bin global histogram (512 threads)
// ----------------------------------------------------------------------------
__global__ __launch_bounds__(NBINS)
void scanP_kernel()
{
    __shared__ unsigned ws[WARPS];
    int lane = threadIdx.x & 31, warp = threadIdx.x >> 5;
    for (int p = 0; p < NPASS; p++) {
        unsigned v = g_gh[p * NBINS + threadIdx.x];
        unsigned x = v;
        #pragma unroll
        for (int o = 1; o < 32; o <<= 1) {
            unsigned t = __shfl_up_sync(0xffffffffu, x, o);
            if (lane >= o) x += t;
        }
        if (lane == 31) ws[warp] = x;
        __syncthreads();
        if (warp == 0 && lane < WARPS) {
            unsigned s = ws[lane];
            #pragma unroll
            for (int o = 1; o < WARPS; o <<= 1) {
                unsigned t = __shfl_up_sync(0xffffu, s, o);
                if (lane >= o) s += t;
            }
            ws[lane] = s;
        }
        __syncthreads();
        unsigned wbase = (warp == 0) ? 0u : ws[warp - 1];
        g_base[p * NBINS + threadIdx.x] = wbase + x - v;
        __syncthreads();
    }
}

// ----------------------------------------------------------------------------
// 2b) onesweep scatter: 512 threads, 16 warps x 256-elem chunks, EPT=8,
//     512 bins (tid == digit). Last pass emits index-only (u32).
// ----------------------------------------------------------------------------
__global__ __launch_bounds__(SORT_THREADS)
void scatter_os_kernel(const uint2* __restrict__ kvin,
                       uint2* __restrict__ kvout,
                       unsigned* __restrict__ iout,
                       int n, int shift, int pass, int last)
{
    __shared__ unsigned short warpCnt[WARPS][NBINS];
    __shared__ uint2          sKV[SORT_TILE];
    __shared__ unsigned       sGlob[NBINS];
    __shared__ unsigned       sLoc[NBINS];
    __shared__ unsigned       ws[WARPS];

    int tid = threadIdx.x, warp = tid >> 5, lane = tid & 31;
    int bid = blockIdx.x;
    int base = bid * SORT_TILE;
    int m = n - base; if (m > SORT_TILE) m = SORT_TILE;
    unsigned ltmask = (1u << lane) - 1u;

    unsigned* lb = g_lb + (size_t)pass * (MAX_NB * NBINS);

    #pragma unroll
    for (int k = tid; k < WARPS * NBINS; k += SORT_THREADS)
        ((unsigned short*)warpCnt)[k] = 0;
    __syncthreads();

    // --- warp-sequential ranking: warp w owns [base + w*256, +256) ---
    int wbase = base + warp * CHUNK;
    uint2          kv[SORT_EPT];
    unsigned short posw[SORT_EPT];

    #pragma unroll
    for (int r = 0; r < SORT_EPT; r++) {
        int idx = wbase + r * 32 + lane;
        bool valid = (idx < n);
        uint2 v = valid ? kvin[idx] : make_uint2(0u, 0u);
        kv[r] = v;
        unsigned d = (v.x >> shift) & 511u;
        unsigned vm    = __ballot_sync(0xffffffffu, valid);
        unsigned peers = __match_any_sync(0xffffffffu, d) & vm;
        unsigned rank  = __popc(peers & ltmask);
        int leader = __ffs(peers) - 1;
        unsigned cbase = 0;
        if (valid && lane == (unsigned)leader) {
            cbase = warpCnt[warp][d];
            warpCnt[warp][d] = (unsigned short)(cbase + __popc(peers));
        }
        cbase = __shfl_sync(0xffffffffu, cbase, leader & 31);
        posw[r] = (unsigned short)(cbase + rank);
        __syncwarp(0xffffffffu);
    }
    __syncthreads();

    // --- block digit totals + per-warp offsets (thread tid owns digit tid) ---
    unsigned c[WARPS];
    unsigned cnt = 0;
    #pragma unroll
    for (int w = 0; w < WARPS; w++) { c[w] = warpCnt[w][tid]; cnt += c[w]; }

    atomicExch(&lb[(size_t)bid * NBINS + tid],
               cnt | (bid == 0 ? INC_FLAG : AGG_FLAG));

    unsigned x = cnt;
    #pragma unroll
    for (int o = 1; o < 32; o <<= 1) {
        unsigned t = __shfl_up_sync(0xffffffffu, x, o);
        if (lane >= o) x += t;
    }
    if (lane == 31) ws[warp] = x;
    __syncthreads();
    if (warp == 0 && lane < WARPS) {
        unsigned s = ws[lane];
        #pragma unroll
        for (int o = 1; o < WARPS; o <<= 1) {
            unsigned t = __shfl_up_sync(0xffffu, s, o);
            if (lane >= o) s += t;
        }
        ws[lane] = s;
    }
    __syncthreads();
    {
        unsigned wb = (warp == 0) ? 0u : ws[warp - 1];
        unsigned loc = wb + x - cnt;
        sLoc[tid] = loc;
        unsigned acc = loc;
        #pragma unroll
        for (int w = 0; w < WARPS; w++) { warpCnt[w][tid] = (unsigned short)acc; acc += c[w]; }
    }
    __syncthreads();

    #pragma unroll
    for (int r = 0; r < SORT_EPT; r++) {
        int idx = wbase + r * 32 + lane;
        if (idx < n) {
            unsigned d = (kv[r].x >> shift) & 511u;
            unsigned p = (unsigned)warpCnt[warp][d] + (unsigned)posw[r];
            sKV[p] = kv[r];
        }
    }

    // --- decoupled lookback (thread tid owns digit tid) ---
    {
        unsigned excl = 0;
        if (bid > 0) {
            volatile unsigned* vlb = (volatile unsigned*)lb;
            int j = bid - 1;
            bool done = false;
            while (!done) {
                unsigned sv[8];
                int take = (j + 1 < 8) ? (j + 1) : 8;
                #pragma unroll
                for (int t = 0; t < 8; t++)
                    if (t < take) sv[t] = vlb[(size_t)(j - t) * NBINS + tid];
                for (int t = 0; t < take; t++) {
                    unsigned v = sv[t];
                    while (v < AGG_FLAG) v = vlb[(size_t)(j - t) * NBINS + tid];
                    excl += v & VAL_MASK;
                    if (v >= INC_FLAG) { done = true; break; }
                }
                j -= take;
                if (j < 0) done = true;
            }
            atomicExch(&lb[(size_t)bid * NBINS + tid], (excl + cnt) | INC_FLAG);
        }
        sGlob[tid] = g_base[pass * NBINS + tid] + excl;
    }
    __syncthreads();

    // --- coalesced emit ---
    if (last) {
        for (int j = tid; j < m; j += SORT_THREADS) {
            uint2 v = sKV[j];
            unsigned d = (v.x >> shift) & 511u;
            iout[sGlob[d] + ((unsigned)j - sLoc[d])] = v.y;
        }
    } else {
        for (int j = tid; j < m; j += SORT_THREADS) {
            uint2 v = sKV[j];
            unsigned d = (v.x >> shift) & 511u;
            kvout[sGlob[d] + ((unsigned)j - sLoc[d])] = v;
        }
    }
}

// ----------------------------------------------------------------------------
// 3) finalize: gather one 64B packed row per sorted element, recompute the
//    21 outputs, stage in shared (stride 21 -> conflict-free), flush coalesced
// ----------------------------------------------------------------------------
__global__ __launch_bounds__(256)
void finalize_kernel(const unsigned* __restrict__ sidx,
                     const float* __restrict__ V,
                     const float* __restrict__ F,
                     const float* __restrict__ tanxp,
                     const float* __restrict__ tanyp,
                     const float* __restrict__ fxp,
                     const float* __restrict__ fyp,
                     const int*   __restrict__ wptr,
                     const int*   __restrict__ hptr,
                     float* __restrict__ out,
                     int n)
{
    __shared__ float st[256 * NCOLS];

    int r = blockIdx.x * blockDim.x + threadIdx.x;

    if (r < n) {
        unsigned li = sidx[r];
        const float4* src = g_pk + (size_t)li * 4;
        float4 r0 = src[0];
        float4 r1 = src[1];
        float4 r2 = src[2];
        float4 r3 = src[3];

        float px_ = r0.x, py_ = r0.y, pz_ = r0.z;
        float qw = r0.w, qx = r1.x, qy = r1.y, qz = r1.z;
        float s0 = r1.w, s1 = r2.x, s2 = r2.y;
        float c0c = r2.z, c1c = r2.w, c2c = r3.x;
        float o = r3.y;

        float tanX = tanxp[0], tanY = tanyp[0];
        float fx = fxp[0], fy = fyp[0];
        float Wd = (float)wptr[0];
        float Hd = (float)hptr[0];

        float qn = rsqrtf(qw*qw + qx*qx + qy*qy + qz*qz);
        qw *= qn; qx *= qn; qy *= qn; qz *= qn;
        float R00 = 1.f - 2.f*(qy*qy + qz*qz);
        float R01 = 2.f*(qx*qy - qw*qz);
        float R02 = 2.f*(qx*qz + qw*qy);
        float R10 = 2.f*(qx*qy + qw*qz);
        float R11 = 1.f - 2.f*(qx*qx + qz*qz);
        float R12 = 2.f*(qy*qz - qw*qx);
        float R20 = 2.f*(qx*qz - qw*qy);
        float R21 = 2.f*(qy*qz + qw*qx);
        float R22 = 1.f - 2.f*(qx*qx + qy*qy);

        float M00 = R00*s0, M01 = R01*s1, M02 = R02*s2;
        float M10 = R10*s0, M11 = R11*s1, M12 = R12*s2;
        float M20 = R20*s0, M21 = R21*s1, M22 = R22*s2;
        float C00 = M00*M00 + M01*M01 + M02*M02;
        float C01 = M00*M10 + M01*M11 + M02*M12;
        float C02 = M00*M20 + M01*M21 + M02*M22;
        float C11 = M10*M10 + M11*M11 + M12*M12;
        float C12 = M10*M20 + M11*M21 + M12*M22;
        float C22 = M20*M20 + M21*M21 + M22*M22;

        float pvx = px_*V[0] + py_*V[4] + pz_*V[8]  + V[12];
        float pvy = px_*V[1] + py_*V[5] + pz_*V[9]  + V[13];
        float pvz = px_*V[2] + py_*V[6] + pz_*V[10] + V[14];
        float zview = pvz;
        bool in_view = (zview >= 0.2f);

        float cx = px_*F[0] + py_*F[4] + pz_*F[8]  + F[12];
        float cy = px_*F[1] + py_*F[5] + pz_*F[9]  + F[13];
        float cw = px_*F[3] + py_*F[7] + pz_*F[11] + F[15];
        float ndx = cx / cw;
        float ndy = cy / cw;
        float px = ((ndx + 1.f) * Wd - 1.f) * 0.5f;
        float py = ((ndy + 1.f) * Hd - 1.f) * 0.5f;

        float limx = 1.3f * tanX, limy = 1.3f * tanY;
        float xc = fminf(fmaxf(pvx / zview, -limx), limx) * zview;
        float yc = fminf(fmaxf(pvy / zview, -limy), limy) * zview;
        float z2 = zview * zview;

        float J00 = fx / zview;
        float J02 = -(fx * xc) / z2;
        float J11 = fy / zview;
        float J12 = -(fy * yc) / z2;

        float T00 = J00*V[0] + J02*V[2];
        float T01 = J00*V[4] + J02*V[6];
        float T02 = J00*V[8] + J02*V[10];
        float T10 = J11*V[1] + J12*V[2];
        float T11 = J11*V[5] + J12*V[6];
        float T12 = J11*V[9] + J12*V[10];

        float a00 = T00*C00 + T01*C01 + T02*C02;
        float a01 = T00*C01 + T01*C11 + T02*C12;
        float a02 = T00*C02 + T01*C12 + T02*C22;
        float a10 = T10*C00 + T11*C01 + T12*C02;
        float a11 = T10*C01 + T11*C11 + T12*C12;
        float a12 = T10*C02 + T11*C12 + T12*C22;

        float c00 = a00*T00 + a01*T01 + a02*T02;
        float c01 = a00*T10 + a01*T11 + a02*T12;
        float c10 = a10*T00 + a11*T01 + a12*T02;
        float c11 = a10*T10 + a11*T11 + a12*T12;

        float det = c00*c11 - c01*c10;
        float det_safe = (fabsf(det) < 1e-6f) ? 1e-6f : det;
        float ic0 =  c11 / det_safe;
        float ic1 = -c01 / det_safe;
        float ic2 = -c10 / det_safe;
        float ic3 =  c00 / det_safe;

        float mid = 0.5f * (c00 + c11);
        float inter = fmaxf(mid*mid - det, 0.1f);
        float lam = mid + sqrtf(inter);
        float radius = ceilf(3.0f * sqrtf(fmaxf(lam, 0.f)));
        float min_x = floorf(px - radius);
        float min_y = floorf(py - radius);
        float max_x = ceilf(px + radius);
        float max_y = ceilf(py + radius);

        float sig;
        if (o >= 0.f) { sig = 1.f / (1.f + expf(-o)); }
        else          { float e = expf(o); sig = e / (1.f + e); }

        float* row = st + threadIdx.x * NCOLS;
        row[0]  = px;     row[1]  = py;     row[2]  = zview;
        row[3]  = c00;    row[4]  = c01;    row[5]  = c10;    row[6] = c11;
        row[7]  = ic0;    row[8]  = ic1;    row[9]  = ic2;    row[10] = ic3;
        row[11] = radius;
        row[12] = min_x;  row[13] = min_y;  row[14] = max_x;  row[15] = max_y;
        row[16] = c0c;    row[17] = c1c;    row[18] = c2c;
        row[19] = sig;
        row[20] = in_view ? 1.f : 0.f;
    }
    __syncthreads();

    size_t base = (size_t)blockIdx.x * 256 * NCOLS;
    size_t limit = (size_t)n * NCOLS;
    #pragma unroll 3
    for (int k = threadIdx.x; k < 256 * NCOLS; k += 256) {
        size_t g = base + k;
        if (g < limit) out[g] = st[k];
    }
}

// ----------------------------------------------------------------------------
extern "C" void kernel_launch(void* const* d_in, const int* in_sizes, int n_in,
                              void* d_out, int out_size)
{
    const float* pts  = (const float*)d_in[0];
    const float* cols = (const float*)d_in[1];
    const float* opa  = (const float*)d_in[2];
    const float* scl  = (const float*)d_in[3];
    const float* quat = (const float*)d_in[4];
    const float* V    = (const float*)d_in[5];
    const float* F    = (const float*)d_in[6];
    const float* tanx = (const float*)d_in[7];
    const float* tany = (const float*)d_in[8];
    const float* fx   = (const float*)d_in[9];
    const float* fy   = (const float*)d_in[10];
    const int*   wp   = (const int*)d_in[11];
    const int*   hp   = (const int*)d_in[12];
    float* out = (float*)d_out;

    int n = in_sizes[2];
    if (n <= 0 || n > N_MAX) return;
    (void)n_in; (void)out_size;

    static uint2 *kvA = nullptr, *kvB = nullptr;
    static unsigned *idxp = nullptr;
    static void *lbp = nullptr, *ghp = nullptr;
    if (!kvA) {
        cudaGetSymbolAddress((void**)&kvA, g_kvA);
        cudaGetSymbolAddress((void**)&kvB, g_kvB);
        cudaGetSymbolAddress((void**)&idxp, g_idx);
        cudaGetSymbolAddress(&lbp, g_lb);
        cudaGetSymbolAddress(&ghp, g_gh);
    }

    int nb = (n + SORT_TILE - 1) / SORT_TILE;
    int blocks = (n + 255) / 256;

    cudaMemsetAsync(lbp, 0, sizeof(unsigned) * NPASS * MAX_NB * NBINS);
    cudaMemsetAsync(ghp, 0, sizeof(unsigned) * NPASS * NBINS);

    prep_kernel<<<blocks, 256>>>(pts, cols, opa, scl, quat, V, n);
    scanP_kernel<<<1, NBINS>>>();

    uint2* kin = kvA;  uint2* kout = kvB;
    for (int p = 0; p < NPASS; p++) {
        int last = (p == NPASS - 1);
        scatter_os_kernel<<<nb, SORT_THREADS>>>(kin, kout, idxp,
                                                n, p * 9, p, last);
        uint2* t = kin; kin = kout; kout = t;
    }

    finalize_kernel<<<blocks, 256>>>(idxp, V, F, tanx, tany, fx, fy, wp, hp,
                                     out, n);
}

// round 14
// speedup vs baseline: 2.1304x; 1.0088x over previous
#include <cuda_runtime.h>
#include <math.h>
#include <stdint.h>

// ----------------------------------------------------------------------------
// GaussianScene: prep(pack 64B rows + key + hist) -> 3x9-bit onesweep sort
// (8192-elem tiles, dynamic smem, last pass emits index-only) -> finalize
// (gather 64B row, recompute, coalesced store).
// Key remap: in-view zview bit patterns lie in [0x3E4CCCCD, 0x41800000)
// (zview in [0.2,16)); key27 = bits - 0x3E000000 < 2^26. out-of-view -> max.
// ----------------------------------------------------------------------------

#define N_MAX   2100000
#define NCOLS   21
#define SORT_THREADS 512
#define WARPS   16
#define SORT_EPT     16
#define SORT_TILE    (SORT_THREADS * SORT_EPT)   // 8192
#define CHUNK   (SORT_TILE / WARPS)              // 512 per warp
#define MAX_NB  ((N_MAX + SORT_TILE - 1) / SORT_TILE + 1)
#define NBINS   512
#define NPASS   3

// dynamic shared layout (bytes)
#define SH_KV_OFF    0                              // uint2[8192] = 65536
#define SH_WC_OFF    65536                          // u16[16][512] = 16384
#define SH_GLOB_OFF  (65536 + 16384)                // u32[512] = 2048
#define SH_LOC_OFF   (SH_GLOB_OFF + 2048)           // u32[512] = 2048
#define SH_WS_OFF    (SH_LOC_OFF + 2048)            // u32[16]  = 64
#define SH_TOTAL     (SH_WS_OFF + 64)               // 86080

#define AGG_FLAG 0x40000000u
#define INC_FLAG 0x80000000u
#define VAL_MASK 0x3FFFFFFFu

__device__ float4   g_pk[(size_t)N_MAX * 4];        // 64B packed input rows
__device__ uint2    g_kvA[N_MAX];
__device__ uint2    g_kvB[N_MAX];
__device__ unsigned g_idx[N_MAX];                   // final sorted indices
__device__ unsigned g_lb[NPASS * MAX_NB * NBINS];   // lookback status (memset 0)
__device__ unsigned g_gh[NPASS * NBINS];            // global digit hists (memset 0)
__device__ unsigned g_base[NPASS * NBINS];          // exclusive digit bases

__device__ __forceinline__ void wagg_add(unsigned* bin, unsigned d, unsigned am, int lane)
{
    unsigned peers = __match_any_sync(am, d);
    int leader = __ffs(peers) - 1;
    if (lane == leader) atomicAdd(&bin[d], (unsigned)__popc(peers));
}

// ----------------------------------------------------------------------------
// 1) prep: pack 16-float input row + depth key + fused 3-pass histogram
// ----------------------------------------------------------------------------
__global__ __launch_bounds__(256)
void prep_kernel(const float* __restrict__ pts,
                 const float* __restrict__ cols,
                 const float* __restrict__ opa,
                 const float* __restrict__ scl,
                 const float* __restrict__ quat,
                 const float* __restrict__ V,
                 int n)
{
    __shared__ unsigned h[NPASS * NBINS];
    #pragma unroll
    for (int k = threadIdx.x; k < NPASS * NBINS; k += 256) h[k] = 0;
    __syncthreads();

    int i = blockIdx.x * blockDim.x + threadIdx.x;
    int lane = threadIdx.x & 31;

    if (i < n) {
        float px_ = pts[3*i+0], py_ = pts[3*i+1], pz_ = pts[3*i+2];
        float4 q  = ((const float4*)quat)[i];
        float s0 = scl[3*i+0], s1 = scl[3*i+1], s2 = scl[3*i+2];
        float c0 = cols[3*i+0], c1 = cols[3*i+1], c2 = cols[3*i+2];
        float o  = opa[i];

        float zview = px_*V[2] + py_*V[6] + pz_*V[10] + V[14];
        bool in_view = (zview >= 0.2f);
        unsigned k;
        if (in_view) {
            unsigned b = __float_as_uint(zview);
            k = (b >= 0x41800000u) ? 0x07FFFFFEu : (b - 0x3E000000u);
        } else {
            k = 0x07FFFFFFu;
        }
        g_kvA[i] = make_uint2(k, (unsigned)i);

        float4* dst = g_pk + (size_t)i * 4;
        dst[0] = make_float4(px_, py_, pz_, q.x);
        dst[1] = make_float4(q.y, q.z, q.w, s0);
        dst[2] = make_float4(s1, s2, c0, c1);
        dst[3] = make_float4(c2, o, 0.f, 0.f);

        unsigned am = __activemask();
        wagg_add(&h[0*NBINS], k         & 511u, am, lane);
        wagg_add(&h[1*NBINS], (k >> 9)  & 511u, am, lane);
        wagg_add(&h[2*NBINS], (k >> 18) & 511u, am, lane);
    }
    __syncthreads();

    #pragma unroll
    for (int k = threadIdx.x; k < NPASS * NBINS; k += 256) {
        unsigned c = h[k];
        if (c) atomicAdd(&g_gh[k], c);
    }
}

// ----------------------------------------------------------------------------
// 2a) exclusive scan of each pass's 512-bin global histogram (512 threads)
// ----------------------------------------------------------------------------
__global__ __launch_bounds__(NBINS)
void scanP_kernel()
{
    __shared__ unsigned ws[WARPS];
    int lane = threadIdx.x & 31, warp = threadIdx.x >> 5;
    for (int p = 0; p < NPASS; p++) {
        unsigned v = g_gh[p * NBINS + threadIdx.x];
        unsigned x = v;
        #pragma unroll
        for (int o = 1; o < 32; o <<= 1) {
            unsigned t = __shfl_up_sync(0xffffffffu, x, o);
            if (lane >= o) x += t;
        }
        if (lane == 31) ws[warp] = x;
        __syncthreads();
        if (warp == 0 && lane < WARPS) {
            unsigned s = ws[lane];
            #pragma unroll
            for (int o = 1; o < WARPS; o <<= 1) {
                unsigned t = __shfl_up_sync(0xffffu, s, o);
                if (lane >= o) s += t;
            }
            ws[lane] = s;
        }
        __syncthreads();
        unsigned wbase = (warp == 0) ? 0u : ws[warp - 1];
        g_base[p * NBINS + threadIdx.x] = wbase + x - v;
        __syncthreads();
    }
}

// ----------------------------------------------------------------------------
// 2b) onesweep scatter: 512 threads, 16 warps x 512-elem chunks, EPT=16,
//     8192-elem tiles, dynamic shared. Keys-only ranking phase; place phase
//     re-loads the uint2 from L2. Last pass emits index-only (u32).
// ----------------------------------------------------------------------------
__global__ __launch_bounds__(SORT_THREADS, 2)
void scatter_os_kernel(const uint2* __restrict__ kvin,
                       uint2* __restrict__ kvout,
                       unsigned* __restrict__ iout,
                       int n, int shift, int pass, int last)
{
    extern __shared__ char sh[];
    uint2*          sKV     = (uint2*)(sh + SH_KV_OFF);
    unsigned short* warpCnt = (unsigned short*)(sh + SH_WC_OFF); // [16][512]
    unsigned*       sGlob   = (unsigned*)(sh + SH_GLOB_OFF);
    unsigned*       sLoc    = (unsigned*)(sh + SH_LOC_OFF);
    unsigned*       ws      = (unsigned*)(sh + SH_WS_OFF);

    int tid = threadIdx.x, warp = tid >> 5, lane = tid & 31;
    int bid = blockIdx.x;
    int base = bid * SORT_TILE;
    int m = n - base; if (m > SORT_TILE) m = SORT_TILE;
    unsigned ltmask = (1u << lane) - 1u;

    unsigned* lb = g_lb + (size_t)pass * (MAX_NB * NBINS);

    #pragma unroll
    for (int k = tid; k < WARPS * NBINS; k += SORT_THREADS)
        warpCnt[k] = 0;
    __syncthreads();

    // --- phase A: warp-sequential ranking (keys only) ---
    int wbase = base + warp * CHUNK;
    unsigned short posw[SORT_EPT];

    #pragma unroll
    for (int r = 0; r < SORT_EPT; r++) {
        int idx = wbase + r * 32 + lane;
        bool valid = (idx < n);
        unsigned key = valid ? kvin[idx].x : 0u;
        unsigned d = (key >> shift) & 511u;
        unsigned vm    = __ballot_sync(0xffffffffu, valid);
        unsigned peers = __match_any_sync(0xffffffffu, d) & vm;
        unsigned rank  = __popc(peers & ltmask);
        int leader = __ffs(peers) - 1;
        unsigned cbase = 0;
        if (valid && lane == (unsigned)leader) {
            cbase = warpCnt[warp * NBINS + d];
            warpCnt[warp * NBINS + d] = (unsigned short)(cbase + __popc(peers));
        }
        cbase = __shfl_sync(0xffffffffu, cbase, leader & 31);
        posw[r] = (unsigned short)(cbase + rank);
        __syncwarp(0xffffffffu);
    }
    __syncthreads();

    // --- block digit totals + per-warp offsets (thread tid owns digit tid) ---
    unsigned c[WARPS];
    unsigned cnt = 0;
    #pragma unroll
    for (int w = 0; w < WARPS; w++) { c[w] = warpCnt[w * NBINS + tid]; cnt += c[w]; }

    atomicExch(&lb[(size_t)bid * NBINS + tid],
               cnt | (bid == 0 ? INC_FLAG : AGG_FLAG));

    unsigned x = cnt;
    #pragma unroll
    for (int o = 1; o < 32; o <<= 1) {
        unsigned t = __shfl_up_sync(0xffffffffu, x, o);
        if (lane >= o) x += t;
    }
    if (lane == 31) ws[warp] = x;
    __syncthreads();
    if (warp == 0 && lane < WARPS) {
        unsigned s = ws[lane];
        #pragma unroll
        for (int o = 1; o < WARPS; o <<= 1) {
            unsigned t = __shfl_up_sync(0xffffu, s, o);
            if (lane >= o) s += t;
        }
        ws[lane] = s;
    }
    __syncthreads();
    {
        unsigned wb = (warp == 0) ? 0u : ws[warp - 1];
        unsigned loc = wb + x - cnt;
        sLoc[tid] = loc;
        unsigned acc = loc;
        #pragma unroll
        for (int w = 0; w < WARPS; w++) {
            warpCnt[w * NBINS + tid] = (unsigned short)acc;
            acc += c[w];
        }
    }
    __syncthreads();

    // --- phase B: re-load uint2 from L2 and place at final local position ---
    #pragma unroll
    for (int r = 0; r < SORT_EPT; r++) {
        int idx = wbase + r * 32 + lane;
        if (idx < n) {
            uint2 v = kvin[idx];
            unsigned d = (v.x >> shift) & 511u;
            unsigned p = (unsigned)warpCnt[warp * NBINS + d] + (unsigned)posw[r];
            sKV[p] = v;
        }
    }

    // --- decoupled lookback (thread tid owns digit tid) ---
    {
        unsigned excl = 0;
        if (bid > 0) {
            volatile unsigned* vlb = (volatile unsigned*)lb;
            int j = bid - 1;
            bool done = false;
            while (!done) {
                unsigned sv[8];
                int take = (j + 1 < 8) ? (j + 1) : 8;
                #pragma unroll
                for (int t = 0; t < 8; t++)
                    if (t < take) sv[t] = vlb[(size_t)(j - t) * NBINS + tid];
                for (int t = 0; t < take; t++) {
                    unsigned v = sv[t];
                    while (v < AGG_FLAG) v = vlb[(size_t)(j - t) * NBINS + tid];
                    excl += v & VAL_MASK;
                    if (v >= INC_FLAG) { done = true; break; }
                }
                j -= take;
                if (j < 0) done = true;
            }
            atomicExch(&lb[(size_t)bid * NBINS + tid], (excl + cnt) | INC_FLAG);
        }
        sGlob[tid] = g_base[pass * NBINS + tid] + excl;
    }
    __syncthreads();

    // --- coalesced emit ---
    if (last) {
        for (int j = tid; j < m; j += SORT_THREADS) {
            uint2 v = sKV[j];
            unsigned d = (v.x >> shift) & 511u;
            iout[sGlob[d] + ((unsigned)j - sLoc[d])] = v.y;
        }
    } else {
        for (int j = tid; j < m; j += SORT_THREADS) {
            uint2 v = sKV[j];
            unsigned d = (v.x >> shift) & 511u;
            kvout[sGlob[d] + ((unsigned)j - sLoc[d])] = v;
        }
    }
}

// ----------------------------------------------------------------------------
// 3) finalize: gather one 64B packed row per sorted element, recompute the
//    21 outputs, stage in shared (stride 21 -> conflict-free), flush coalesced
// ----------------------------------------------------------------------------
__global__ __launch_bounds__(256)
void finalize_kernel(const unsigned* __restrict__ sidx,
                     const float* __restrict__ V,
                     const float* __restrict__ F,
                     const float* __restrict__ tanxp,
                     const float* __restrict__ tanyp,
                     const float* __restrict__ fxp,
                     const float* __restrict__ fyp,
                     const int*   __restrict__ wptr,
                     const int*   __restrict__ hptr,
                     float* __restrict__ out,
                     int n)
{
    __shared__ float st[256 * NCOLS];

    int r = blockIdx.x * blockDim.x + threadIdx.x;

    if (r < n) {
        unsigned li = sidx[r];
        const float4* src = g_pk + (size_t)li * 4;
        float4 r0 = src[0];
        float4 r1 = src[1];
        float4 r2 = src[2];
        float4 r3 = src[3];

        float px_ = r0.x, py_ = r0.y, pz_ = r0.z;
        float qw = r0.w, qx = r1.x, qy = r1.y, qz = r1.z;
        float s0 = r1.w, s1 = r2.x, s2 = r2.y;
        float c0c = r2.z, c1c = r2.w, c2c = r3.x;
        float o = r3.y;

        float tanX = tanxp[0], tanY = tanyp[0];
        float fx = fxp[0], fy = fyp[0];
        float Wd = (float)wptr[0];
        float Hd = (float)hptr[0];

        float qn = rsqrtf(qw*qw + qx*qx + qy*qy + qz*qz);
        qw *= qn; qx *= qn; qy *= qn; qz *= qn;
        float R00 = 1.f - 2.f*(qy*qy + qz*qz);
        float R01 = 2.f*(qx*qy - qw*qz);
        float R02 = 2.f*(qx*qz + qw*qy);
        float R10 = 2.f*(qx*qy + qw*qz);
        float R11 = 1.f - 2.f*(qx*qx + qz*qz);
        float R12 = 2.f*(qy*qz - qw*qx);
        float R20 = 2.f*(qx*qz - qw*qy);
        float R21 = 2.f*(qy*qz + qw*qx);
        float R22 = 1.f - 2.f*(qx*qx + qy*qy);

        float M00 = R00*s0, M01 = R01*s1, M02 = R02*s2;
        float M10 = R10*s0, M11 = R11*s1, M12 = R12*s2;
        float M20 = R20*s0, M21 = R21*s1, M22 = R22*s2;
        float C00 = M00*M00 + M01*M01 + M02*M02;
        float C01 = M00*M10 + M01*M11 + M02*M12;
        float C02 = M00*M20 + M01*M21 + M02*M22;
        float C11 = M10*M10 + M11*M11 + M12*M12;
        float C12 = M10*M20 + M11*M21 + M12*M22;
        float C22 = M20*M20 + M21*M21 + M22*M22;

        float pvx = px_*V[0] + py_*V[4] + pz_*V[8]  + V[12];
        float pvy = px_*V[1] + py_*V[5] + pz_*V[9]  + V[13];
        float pvz = px_*V[2] + py_*V[6] + pz_*V[10] + V[14];
        float zview = pvz;
        bool in_view = (zview >= 0.2f);

        float cx = px_*F[0] + py_*F[4] + pz_*F[8]  + F[12];
        float cy = px_*F[1] + py_*F[5] + pz_*F[9]  + F[13];
        float cw = px_*F[3] + py_*F[7] + pz_*F[11] + F[15];
        float ndx = cx / cw;
        float ndy = cy / cw;
        float px = ((ndx + 1.f) * Wd - 1.f) * 0.5f;
        float py = ((ndy + 1.f) * Hd - 1.f) * 0.5f;

        float limx = 1.3f * tanX, limy = 1.3f * tanY;
        float xc = fminf(fmaxf(pvx / zview, -limx), limx) * zview;
        float yc = fminf(fmaxf(pvy / zview, -limy), limy) * zview;
        float z2 = zview * zview;

        float J00 = fx / zview;
        float J02 = -(fx * xc) / z2;
        float J11 = fy / zview;
        float J12 = -(fy * yc) / z2;

        float T00 = J00*V[0] + J02*V[2];
        float T01 = J00*V[4] + J02*V[6];
        float T02 = J00*V[8] + J02*V[10];
        float T10 = J11*V[1] + J12*V[2];
        float T11 = J11*V[5] + J12*V[6];
        float T12 = J11*V[9] + J12*V[10];

        float a00 = T00*C00 + T01*C01 + T02*C02;
        float a01 = T00*C01 + T01*C11 + T02*C12;
        float a02 = T00*C02 + T01*C12 + T02*C22;
        float a10 = T10*C00 + T11*C01 + T12*C02;
        float a11 = T10*C01 + T11*C11 + T12*C12;
        float a12 = T10*C02 + T11*C12 + T12*C22;

        float c00 = a00*T00 + a01*T01 + a02*T02;
        float c01 = a00*T10 + a01*T11 + a02*T12;
        float c10 = a10*T00 + a11*T01 + a12*T02;
        float c11 = a10*T10 + a11*T11 + a12*T12;

        float det = c00*c11 - c01*c10;
        float det_safe = (fabsf(det) < 1e-6f) ? 1e-6f : det;
        float ic0 =  c11 / det_safe;
        float ic1 = -c01 / det_safe;
        float ic2 = -c10 / det_safe;
        float ic3 =  c00 / det_safe;

        float mid = 0.5f * (c00 + c11);
        float inter = fmaxf(mid*mid - det, 0.1f);
        float lam = mid + sqrtf(inter);
        float radius = ceilf(3.0f * sqrtf(fmaxf(lam, 0.f)));
        float min_x = floorf(px - radius);
        float min_y = floorf(py - radius);
        float max_x = ceilf(px + radius);
        float max_y = ceilf(py + radius);

        float sig;
        if (o >= 0.f) { sig = 1.f / (1.f + expf(-o)); }
        else          { float e = expf(o); sig = e / (1.f + e); }

        float* row = st + threadIdx.x * NCOLS;
        row[0]  = px;     row[1]  = py;     row[2]  = zview;
        row[3]  = c00;    row[4]  = c01;    row[5]  = c10;    row[6] = c11;
        row[7]  = ic0;    row[8]  = ic1;    row[9]  = ic2;    row[10] = ic3;
        row[11] = radius;
        row[12] = min_x;  row[13] = min_y;  row[14] = max_x;  row[15] = max_y;
        row[16] = c0c;    row[17] = c1c;    row[18] = c2c;
        row[19] = sig;
        row[20] = in_view ? 1.f : 0.f;
    }
    __syncthreads();

    size_t base = (size_t)blockIdx.x * 256 * NCOLS;
    size_t limit = (size_t)n * NCOLS;
    #pragma unroll 3
    for (int k = threadIdx.x; k < 256 * NCOLS; k += 256) {
        size_t g = base + k;
        if (g < limit) out[g] = st[k];
    }
}

// ----------------------------------------------------------------------------
extern "C" void kernel_launch(void* const* d_in, const int* in_sizes, int n_in,
                              void* d_out, int out_size)
{
    const float* pts  = (const float*)d_in[0];
    const float* cols = (const float*)d_in[1];
    const float* opa  = (const float*)d_in[2];
    const float* scl  = (const float*)d_in[3];
    const float* quat = (const float*)d_in[4];
    const float* V    = (const float*)d_in[5];
    const float* F    = (const float*)d_in[6];
    const float* tanx = (const float*)d_in[7];
    const float* tany = (const float*)d_in[8];
    const float* fx   = (const float*)d_in[9];
    const float* fy   = (const float*)d_in[10];
    const int*   wp   = (const int*)d_in[11];
    const int*   hp   = (const int*)d_in[12];
    float* out = (float*)d_out;

    int n = in_sizes[2];
    if (n <= 0 || n > N_MAX) return;
    (void)n_in; (void)out_size;

    static uint2 *kvA = nullptr, *kvB = nullptr;
    static unsigned *idxp = nullptr;
    static void *lbp = nullptr, *ghp = nullptr;
    if (!kvA) {
        cudaGetSymbolAddress((void**)&kvA, g_kvA);
        cudaGetSymbolAddress((void**)&kvB, g_kvB);
        cudaGetSymbolAddress((void**)&idxp, g_idx);
        cudaGetSymbolAddress(&lbp, g_lb);
        cudaGetSymbolAddress(&ghp, g_gh);
        cudaFuncSetAttribute(scatter_os_kernel,
                             cudaFuncAttributeMaxDynamicSharedMemorySize,
                             SH_TOTAL);
    }

    int nb = (n + SORT_TILE - 1) / SORT_TILE;
    int blocks = (n + 255) / 256;

    cudaMemsetAsync(lbp, 0, sizeof(unsigned) * NPASS * MAX_NB * NBINS);
    cudaMemsetAsync(ghp, 0, sizeof(unsigned) * NPASS * NBINS);

    prep_kernel<<<blocks, 256>>>(pts, cols, opa, scl, quat, V, n);
    scanP_kernel<<<1, NBINS>>>();

    uint2* kin = kvA;  uint2* kout = kvB;
    for (int p = 0; p < NPASS; p++) {
        int last = (p == NPASS - 1);
        scatter_os_kernel<<<nb, SORT_THREADS, SH_TOTAL>>>(kin, kout, idxp,
                                                          n, p * 9, p, last);
        uint2* t = kin; kin = kout; kout = t;
    }

    finalize_kernel<<<blocks, 256>>>(idxp, V, F, tanx, tany, fx, fy, wp, hp,
                                     out, n);
}